// round 1
// baseline (speedup 1.0000x reference)
#include <cuda_runtime.h>
#include <math.h>

#define S_LEN 4096
#define MODEL_D 512
#define NHEAD 8
#define HEAD_D 64

// Scratch (device globals: no allocation allowed in kernel_launch)
__device__ float g_q[S_LEN * MODEL_D];   // [H][S][Dh]
__device__ float g_k[S_LEN * MODEL_D];   // [H][S][Dh]
__device__ float g_v[S_LEN * MODEL_D];   // [H][S][Dh]
__device__ float g_ctx[S_LEN * MODEL_D]; // [S][D]

// ---------------------------------------------------------------------------
// Projection GEMM: out = X @ W, written in per-head layout [H][S][Dh]
// Tiles: BM=64, BN=64, BK=16; 256 threads; 4x4 microtile per thread.
// ---------------------------------------------------------------------------
__global__ __launch_bounds__(256) void proj_kernel(const float* __restrict__ A,
                                                   const float* __restrict__ W,
                                                   int which)
{
    __shared__ float AsT[16][64];
    __shared__ float Bs[16][64];

    float* dst = (which == 0) ? g_q : (which == 1) ? g_k : g_v;

    const int t  = threadIdx.x;
    const int tx = t & 15, ty = t >> 4;
    const int m0 = blockIdx.y * 64, n0 = blockIdx.x * 64;

    float acc[4][4] = {};

    for (int k0 = 0; k0 < MODEL_D; k0 += 16) {
        // A tile 64x16 -> AsT[16][64]
        {
            int ar = t >> 2, ac = (t & 3) << 2;
            float4 a = *(const float4*)&A[(size_t)(m0 + ar) * MODEL_D + k0 + ac];
            AsT[ac + 0][ar] = a.x;
            AsT[ac + 1][ar] = a.y;
            AsT[ac + 2][ar] = a.z;
            AsT[ac + 3][ar] = a.w;
        }
        // B tile 16x64
        {
            int br = t >> 4, bc = (t & 15) << 2;
            *(float4*)&Bs[br][bc] = *(const float4*)&W[(size_t)(k0 + br) * MODEL_D + n0 + bc];
        }
        __syncthreads();
        #pragma unroll
        for (int kk = 0; kk < 16; kk++) {
            float4 av = *(const float4*)&AsT[kk][ty << 2];
            float4 bv = *(const float4*)&Bs[kk][tx << 2];
            float aa[4] = {av.x, av.y, av.z, av.w};
            float bb[4] = {bv.x, bv.y, bv.z, bv.w};
            #pragma unroll
            for (int i = 0; i < 4; i++)
                #pragma unroll
                for (int j = 0; j < 4; j++)
                    acc[i][j] += aa[i] * bb[j];
        }
        __syncthreads();
    }

    // Store per-head: BN==HEAD_D==64, so head = blockIdx.x
    const int head = blockIdx.x;
    #pragma unroll
    for (int i = 0; i < 4; i++) {
        int m = m0 + (ty << 2) + i;
        float4 o = make_float4(acc[i][0], acc[i][1], acc[i][2], acc[i][3]);
        *(float4*)&dst[((size_t)head * S_LEN + m) * HEAD_D + (tx << 2)] = o;
    }
}

// ---------------------------------------------------------------------------
// Flash attention: one block = 64 query rows of one head; 256 threads (16x16).
// Smem: QsT[64][64], KP[64][68] (K^T, then reused for P), Vs[64][64],
//       red[64][17], mn/al/l arrays. Online softmax, O accum in registers.
// ---------------------------------------------------------------------------
#define ATTN_SMEM_FLOATS (4096 + 64*68 + 4096 + 64*17 + 192)
#define ATTN_SMEM_BYTES  (ATTN_SMEM_FLOATS * 4)

__global__ __launch_bounds__(256) void attn_kernel(const float* __restrict__ mask)
{
    extern __shared__ float sm[];
    float* QsT  = sm;                  // [64][64]  (Q^T: [d][row])
    float* KP   = QsT + 4096;          // [64][68]  (K^T: [d][key]) then P: [row][key]
    float* Vs   = KP + 64 * 68;        // [64][64]  ([key][d])
    float* red  = Vs + 4096;           // [64][17]
    float* mn_s = red + 64 * 17;       // [64]
    float* al_s = mn_s + 64;           // [64]
    float* l_s  = al_s + 64;           // [64]

    const int t  = threadIdx.x;
    const int tx = t & 15, ty = t >> 4;
    const int h  = blockIdx.y;
    const int i0 = blockIdx.x * 64;

    const float* Qh = g_q + (size_t)h * S_LEN * HEAD_D;
    const float* Kh = g_k + (size_t)h * S_LEN * HEAD_D;
    const float* Vh = g_v + (size_t)h * S_LEN * HEAD_D;
    const float sc = 1.0f / (8.0f + 1e-9f);

    // Load Q tile transposed: QsT[d][row]
    #pragma unroll
    for (int p = 0; p < 4; p++) {
        int fi  = p * 256 + t;   // float4 index
        int row = fi >> 4;
        int c4  = (fi & 15) << 2;
        float4 qv = *(const float4*)&Qh[(size_t)(i0 + row) * HEAD_D + c4];
        QsT[(c4 + 0) * 64 + row] = qv.x;
        QsT[(c4 + 1) * 64 + row] = qv.y;
        QsT[(c4 + 2) * 64 + row] = qv.z;
        QsT[(c4 + 3) * 64 + row] = qv.w;
    }

    float m_r = -INFINITY, l_r = 0.0f;  // valid in threads t < 64 (row t)
    float accO[4][4] = {};

    for (int j0 = 0; j0 < S_LEN; j0 += 64) {
        __syncthreads();  // prior-iter P/V reads done before overwrite
        // Load K^T into KP and V into Vs
        #pragma unroll
        for (int p = 0; p < 4; p++) {
            int fi  = p * 256 + t;
            int row = fi >> 4;
            int c4  = (fi & 15) << 2;
            float4 kv = *(const float4*)&Kh[(size_t)(j0 + row) * HEAD_D + c4];
            KP[(c4 + 0) * 68 + row] = kv.x;
            KP[(c4 + 1) * 68 + row] = kv.y;
            KP[(c4 + 2) * 68 + row] = kv.z;
            KP[(c4 + 3) * 68 + row] = kv.w;
            *(float4*)&Vs[row * 64 + c4] = *(const float4*)&Vh[(size_t)(j0 + row) * HEAD_D + c4];
        }
        __syncthreads();

        // S = Q @ K^T  (inner dim = Dh = 64)
        float s[4][4] = {};
        #pragma unroll 8
        for (int d = 0; d < 64; d++) {
            float4 av = *(const float4*)&QsT[d * 64 + (ty << 2)];
            float4 bv = *(const float4*)&KP[d * 68 + (tx << 2)];
            float aa[4] = {av.x, av.y, av.z, av.w};
            float bb[4] = {bv.x, bv.y, bv.z, bv.w};
            #pragma unroll
            for (int i = 0; i < 4; i++)
                #pragma unroll
                for (int j = 0; j < 4; j++)
                    s[i][j] += aa[i] * bb[j];
        }

        // scale + mask
        #pragma unroll
        for (int i = 0; i < 4; i++) {
            int gr = i0 + (ty << 2) + i;
            float4 mk = *(const float4*)&mask[(size_t)gr * S_LEN + j0 + (tx << 2)];
            s[i][0] = s[i][0] * sc + mk.x * -1e9f;
            s[i][1] = s[i][1] * sc + mk.y * -1e9f;
            s[i][2] = s[i][2] * sc + mk.z * -1e9f;
            s[i][3] = s[i][3] * sc + mk.w * -1e9f;
        }

        // partial row max
        #pragma unroll
        for (int i = 0; i < 4; i++) {
            float mx = fmaxf(fmaxf(s[i][0], s[i][1]), fmaxf(s[i][2], s[i][3]));
            red[((ty << 2) + i) * 17 + tx] = mx;
        }
        __syncthreads();
        if (t < 64) {
            float mt = red[t * 17];
            #pragma unroll
            for (int k = 1; k < 16; k++) mt = fmaxf(mt, red[t * 17 + k]);
            float mnew = fmaxf(m_r, mt);
            float al = __expf(m_r - mnew);
            m_r = mnew;
            mn_s[t] = mnew;
            al_s[t] = al;
        }
        __syncthreads();

        // exp -> P (into KP, now [row][key] stride 68), partial row sums, rescale O
        #pragma unroll
        for (int i = 0; i < 4; i++) {
            int r = (ty << 2) + i;
            float mnew = mn_s[r];
            float al   = al_s[r];
            float p0 = __expf(s[i][0] - mnew);
            float p1 = __expf(s[i][1] - mnew);
            float p2 = __expf(s[i][2] - mnew);
            float p3 = __expf(s[i][3] - mnew);
            *(float4*)&KP[r * 68 + (tx << 2)] = make_float4(p0, p1, p2, p3);
            red[r * 17 + tx] = p0 + p1 + p2 + p3;
            accO[i][0] *= al; accO[i][1] *= al; accO[i][2] *= al; accO[i][3] *= al;
        }
        __syncthreads();
        if (t < 64) {
            float ssum = 0.0f;
            #pragma unroll
            for (int k = 0; k < 16; k++) ssum += red[t * 17 + k];
            l_r = l_r * al_s[t] + ssum;
        }

        // O += P @ V
        #pragma unroll 8
        for (int c = 0; c < 64; c++) {
            float4 bv = *(const float4*)&Vs[c * 64 + (tx << 2)];
            float bb[4] = {bv.x, bv.y, bv.z, bv.w};
            #pragma unroll
            for (int i = 0; i < 4; i++) {
                float a = KP[((ty << 2) + i) * 68 + c];
                accO[i][0] += a * bb[0];
                accO[i][1] += a * bb[1];
                accO[i][2] += a * bb[2];
                accO[i][3] += a * bb[3];
            }
        }
    }

    if (t < 64) l_s[t] = l_r;
    __syncthreads();

    #pragma unroll
    for (int i = 0; i < 4; i++) {
        int r = (ty << 2) + i;
        float inv = 1.0f / l_s[r];
        float4 o = make_float4(accO[i][0] * inv, accO[i][1] * inv,
                               accO[i][2] * inv, accO[i][3] * inv);
        *(float4*)&g_ctx[(size_t)(i0 + r) * MODEL_D + h * HEAD_D + (tx << 2)] = o;
    }
}

// ---------------------------------------------------------------------------
// Output projection: out = ctx @ Wo + bo  (row-major [S][D])
// ---------------------------------------------------------------------------
__global__ __launch_bounds__(256) void out_kernel(const float* __restrict__ W,
                                                  const float* __restrict__ bias,
                                                  float* __restrict__ out)
{
    __shared__ float AsT[16][64];
    __shared__ float Bs[16][64];

    const int t  = threadIdx.x;
    const int tx = t & 15, ty = t >> 4;
    const int m0 = blockIdx.y * 64, n0 = blockIdx.x * 64;

    float acc[4][4] = {};

    for (int k0 = 0; k0 < MODEL_D; k0 += 16) {
        {
            int ar = t >> 2, ac = (t & 3) << 2;
            float4 a = *(const float4*)&g_ctx[(size_t)(m0 + ar) * MODEL_D + k0 + ac];
            AsT[ac + 0][ar] = a.x;
            AsT[ac + 1][ar] = a.y;
            AsT[ac + 2][ar] = a.z;
            AsT[ac + 3][ar] = a.w;
        }
        {
            int br = t >> 4, bc = (t & 15) << 2;
            *(float4*)&Bs[br][bc] = *(const float4*)&W[(size_t)(k0 + br) * MODEL_D + n0 + bc];
        }
        __syncthreads();
        #pragma unroll
        for (int kk = 0; kk < 16; kk++) {
            float4 av = *(const float4*)&AsT[kk][ty << 2];
            float4 bv = *(const float4*)&Bs[kk][tx << 2];
            float aa[4] = {av.x, av.y, av.z, av.w};
            float bb[4] = {bv.x, bv.y, bv.z, bv.w};
            #pragma unroll
            for (int i = 0; i < 4; i++)
                #pragma unroll
                for (int j = 0; j < 4; j++)
                    acc[i][j] += aa[i] * bb[j];
        }
        __syncthreads();
    }

    const int n = n0 + (tx << 2);
    float4 b4 = *(const float4*)&bias[n];
    #pragma unroll
    for (int i = 0; i < 4; i++) {
        int m = m0 + (ty << 2) + i;
        float4 o = make_float4(acc[i][0] + b4.x, acc[i][1] + b4.y,
                               acc[i][2] + b4.z, acc[i][3] + b4.w);
        *(float4*)&out[(size_t)m * MODEL_D + n] = o;
    }
}

// ---------------------------------------------------------------------------
extern "C" void kernel_launch(void* const* d_in, const int* in_sizes, int n_in,
                              void* d_out, int out_size)
{
    const float* q    = (const float*)d_in[0];
    const float* k    = (const float*)d_in[1];
    const float* v    = (const float*)d_in[2];
    const float* mask = (const float*)d_in[3];
    const float* wq   = (const float*)d_in[4];
    const float* wk   = (const float*)d_in[5];
    const float* wv   = (const float*)d_in[6];
    const float* wo   = (const float*)d_in[7];
    const float* bo   = (const float*)d_in[8];
    float* out = (float*)d_out;

    cudaFuncSetAttribute(attn_kernel, cudaFuncAttributeMaxDynamicSharedMemorySize,
                         ATTN_SMEM_BYTES);

    dim3 gemm_grid(MODEL_D / 64, S_LEN / 64);
    proj_kernel<<<gemm_grid, 256>>>(q, wq, 0);
    proj_kernel<<<gemm_grid, 256>>>(k, wk, 1);
    proj_kernel<<<gemm_grid, 256>>>(v, wv, 2);

    dim3 attn_grid(S_LEN / 64, NHEAD);
    attn_kernel<<<attn_grid, 256, ATTN_SMEM_BYTES>>>(mask);

    out_kernel<<<gemm_grid, 256>>>(wo, bo, out);
}